// round 17
// baseline (speedup 1.0000x reference)
#include <cuda_runtime.h>
#include <cuda_fp16.h>
#include <math.h>
#include <stdint.h>

// CustomLSTM: 2-layer LSTM, B=128, T=512, IN=64, H=1024, OUT=1
// Round 15: fused supersteps [L1(t) | L0(t+1)] in ONE continuous cp.async
// pipeline (all sources safe after the per-step grid barrier -> no gating
// waits, one drain/step), pair-granularity commits/waits/syncs (13/step).
// fp16 HMMA, single-plane act + weights, x exact via hi|lo column trick.

#define Bb    128
#define Tt    512
#define INP   64
#define Hh    1024
#define NBLK  128
#define NTHR  256

typedef unsigned int u32;
typedef unsigned short us;
typedef unsigned long long u64;

// ---- smem layout (bytes) ----
// stage: Act[128 rows][272B] @0 (34816), W[32][272B] @34816 (8704)
#define STG_B    43520u
#define NSTG     4
#define SGATE_B  (NSTG * STG_B)            // 174080: float gate buffer [32][132]
#define HSTG_B   (SGATE_B + 16896u)        // 190976: h staging fp16 [128][8]
#define DYN_SMEM (HSTG_B + 2048u + 256u)   // 193280 bytes

// ---------------- device scratch ----------------
__device__ __align__(128) us d_h0[2][Bb][Hh];      // fp16 bits, single plane
__device__ __align__(128) us d_h1[2][Bb][Hh];
__device__ __align__(128) us d_x[Tt][2][Bb][INP];  // fp16 hi/lo planes
__device__ __align__(128) us d_w[128u * 25u * 32u * 128u];  // [cta][chunk][32][128]
__device__ float d_bias0[4096], d_bias1[4096];
__device__ float d_bi0[Bb * Hh], d_bi1[Bb * Hh];
__device__ float d_h1f[Bb * Hh];
__device__ u32 g_count;
__device__ volatile u32 g_gen;
__device__ volatile u32 g_abort;

// ---------------- helpers ----------------
__device__ __forceinline__ u32 smem_u32(const void* p) {
    u32 a; asm("{ .reg .u64 t; cvta.to.shared.u64 t, %1; cvt.u32.u64 %0, t; }" : "=r"(a) : "l"(p));
    return a;
}
__device__ __forceinline__ void cpa16(u32 dst, const void* src) {
    asm volatile("cp.async.cg.shared.global [%0], [%1], 16;" :: "r"(dst), "l"(src));
}
#define CP_COMMIT() asm volatile("cp.async.commit_group;" ::: "memory")
#define CP_WAIT0()  asm volatile("cp.async.wait_group 0;" ::: "memory")
#define CP_WAIT1()  asm volatile("cp.async.wait_group 1;" ::: "memory")

__device__ __forceinline__ void ldsm4(u32* r, u32 addr) {
    asm volatile("ldmatrix.sync.aligned.m8n8.x4.shared.b16 {%0,%1,%2,%3}, [%4];"
                 : "=r"(r[0]), "=r"(r[1]), "=r"(r[2]), "=r"(r[3]) : "r"(addr));
}
__device__ __forceinline__ void mma_f16(float* c, const u32* a, u32 b0, u32 b1) {
    asm volatile("mma.sync.aligned.m16n8k16.row.col.f32.f16.f16.f32 "
                 "{%0,%1,%2,%3}, {%4,%5,%6,%7}, {%8,%9}, {%0,%1,%2,%3};"
                 : "+f"(c[0]), "+f"(c[1]), "+f"(c[2]), "+f"(c[3])
                 : "r"(a[0]), "r"(a[1]), "r"(a[2]), "r"(a[3]), "r"(b0), "r"(b1));
}

__device__ __forceinline__ float sigf(float x) { return __fdividef(1.f, 1.f + __expf(-x)); }
__device__ __forceinline__ float tanh_f(float x) {
    float xc = fminf(fmaxf(x, -15.f), 15.f);
    float e  = __expf(-2.f * xc);
    return (1.f - e) * __fdividef(1.f, 1.f + e);
}
__device__ __forceinline__ void hsplit(float v, us& hi, us& lo) {
    __half h = __float2half_rn(v);
    __half l = __float2half_rn(v - __half2float(h));
    hi = __half_as_ushort(h); lo = __half_as_ushort(l);
}

// ---------------- setup kernels ----------------
__global__ void setup_misc(const float* __restrict__ boundary,
                           const float* __restrict__ bx0, const float* __restrict__ bh0,
                           const float* __restrict__ bb0, const float* __restrict__ Wb0,
                           const float* __restrict__ bx1, const float* __restrict__ bh1,
                           const float* __restrict__ bb1, const float* __restrict__ Wb1)
{
    int idx = blockIdx.x * 256 + threadIdx.x;   // 131072
    if (idx == 0) { g_count = 0; g_gen = 0; g_abort = 0; }
    ((u32*)d_h0)[idx] = 0u;
    ((u32*)d_h1)[idx] = 0u;
    int b = idx >> 10, j = idx & 1023;
    float p0 = boundary[b * 2 + 0], p1 = boundary[b * 2 + 1];
    d_bi0[idx] = p0 * Wb0[j * 2 + 0] + p1 * Wb0[j * 2 + 1] + bb0[j];
    d_bi1[idx] = p0 * Wb1[j * 2 + 0] + p1 * Wb1[j * 2 + 1] + bb1[j];
    if (idx < 4096) {
        d_bias0[idx] = bx0[idx] + bh0[idx];
        d_bias1[idx] = bx1[idx] + bh1[idx];
    }
}

__global__ void setup_x(const float* __restrict__ x)
{
    int idx = blockIdx.x * 256 + threadIdx.x;   // 4194304
    int k = idx & 63, b = (idx >> 6) & 127, t = idx >> 13;
    float v = x[b * (Tt * INP) + t * INP + k];
    us hi, lo; hsplit(v, hi, lo);
    d_x[t][0][b][k] = hi;
    d_x[t][1][b][k] = lo;
}

// chunk wc: 0-7 Uh0 (K128) | 8 x-special (Wx0 duplicated across halves) |
//           9-16 Wx1 (K128) | 17-24 Uh1 (K128)     — single fp16 plane
__global__ void repack_w(const float* __restrict__ Uh0, const float* __restrict__ Wx0,
                         const float* __restrict__ Wx1, const float* __restrict__ Uh1)
{
    int idx = blockIdx.x * 256 + threadIdx.x;   // 128*25*32*128 = 13107200
    int k   = idx & 127;
    int r   = (idx >> 7) & 31;
    int wc  = (idx >> 12) % 25;
    int cta = idx / (25 << 12);
    int grow = (r >> 3) * Hh + cta * 8 + (r & 7);
    float wv;
    if (wc == 8)      wv = Wx0[grow * INP + (k & 63)];   // duplicated across halves
    else if (wc < 8)  wv = Uh0[grow * Hh + wc * 128 + k];
    else if (wc < 17) wv = Wx1[grow * Hh + (wc - 9) * 128 + k];
    else              wv = Uh1[grow * Hh + (wc - 17) * 128 + k];
    d_w[((u64)(cta * 25 + wc)) * 4096u + r * 128 + k] =
        __half_as_ushort(__float2half_rn(wv));
}

// ---------------- grid barrier (bounded, abort-safe) ----------------
__device__ __forceinline__ void grid_barrier(u32 target)
{
    __threadfence();
    __syncthreads();
    if (threadIdx.x == 0) {
        u32 old = atomicAdd(&g_count, 1u);
        if (old == NBLK - 1) {
            g_count = 0;
            __threadfence();
            g_gen = target;
        } else {
            u32 i = 0;
            while (g_gen < target) {
                __nanosleep(64);
                if (g_abort) break;
                if (++i > (1u << 24)) { g_abort = 1u; break; }
            }
        }
    }
    __syncthreads();
}

// ---------------- chunk staging ----------------
// layer0 (t): ci 0..7 h0_prev slices (d_h0[t&1]), ci 8 = x(t) special
// layer1 (t): ci 0..7 h0_new (d_h0[(t&1)^1]), ci 8..15 h1_prev (d_h1[t&1])
__device__ __forceinline__ void load_chunk(u32 Sa, int layer, int ci, int t, int cta, int tid)
{
    const int rd = t & 1, wr = rd ^ 1;
    const int wc = layer ? (9 + ci) : ci;

    if (layer == 0 && ci == 8) {
        const us* xb = &d_x[t][0][0][0];        // plane stride 8192 us
#pragma unroll
        for (int i = 0; i < 8; ++i) {           // act: 2048 x 16B
            int idx = tid + i * 256;
            int row = idx >> 4, seg = idx & 15;
            const us* src = (seg < 8) ? (xb + row * INP + seg * 8)
                                      : (xb + 8192 + row * INP + (seg - 8) * 8);
            cpa16(Sa + (u32)(row * 272 + seg * 16), src);
        }
    } else {
        const us* aH; int k0;
        if (layer == 0)   { aH = &d_h0[rd][0][0]; k0 = ci * 128; }
        else if (ci < 8)  { aH = &d_h0[wr][0][0]; k0 = ci * 128; }
        else              { aH = &d_h1[rd][0][0]; k0 = (ci - 8) * 128; }
#pragma unroll
        for (int i = 0; i < 8; ++i) {           // act: 2048 x 16B
            int idx = tid + i * 256;
            int row = idx >> 4, seg = idx & 15;
            cpa16(Sa + (u32)(row * 272 + seg * 16), aH + row * Hh + k0 + seg * 8);
        }
    }
    const us* wsrc = d_w + ((u64)(cta * 25 + wc)) * 4096u;
#pragma unroll
    for (int i = 0; i < 2; ++i) {               // W: 512 x 16B
        int idx = tid + i * 256;
        int row = idx >> 4, seg = idx & 15;
        cpa16(Sa + (u32)(34816 + row * 272 + seg * 16),
              wsrc + row * 128 + seg * 8);
    }
}

// superstep chunk m -> load. s>=0: m 0..15 = L1(s), m 16..24 = L0(s+1).
// s<0: m 0..8 = L0(0).
__device__ __forceinline__ void load_m(u32 smA, int s, int m, int cta, int tid)
{
    u32 Sa = smA + (u32)(m & 3) * STG_B;
    if (s >= 0 && m < 16) load_chunk(Sa, 1, m, s, cta, tid);
    else {
        int ci = (s < 0) ? m : (m - 16);
        load_chunk(Sa, 0, ci, s + 1, cta, tid);
    }
}

// ---------------- one K=128 chunk of MMA work ----------------
__device__ __forceinline__ void compute_chunk(u32 SaB, u32 aoffW, u32 boffA, u32 boffB,
                                              float acc[4][4])
{
    const u32 actB = SaB;
    const u32 whB  = SaB + 34816;
    u32 wh[2][4], b1[2][4], b2[2][4];
    ldsm4(wh[0], whB  + aoffW);
    ldsm4(b1[0], actB + boffA);
    ldsm4(b2[0], actB + boffB);
    int cur = 0;
#pragma unroll
    for (int kk = 0; kk < 8; ++kk) {
        const int nxt = cur ^ 1;
        if (kk < 7) {
            const u32 kb = (u32)(kk + 1) * 32;
            ldsm4(wh[nxt], whB  + aoffW + kb);
            ldsm4(b1[nxt], actB + boffA + kb);
            ldsm4(b2[nxt], actB + boffB + kb);
        }
        mma_f16(acc[0], wh[cur], b1[cur][0], b1[cur][1]);
        mma_f16(acc[1], wh[cur], b1[cur][2], b1[cur][3]);
        mma_f16(acc[2], wh[cur], b2[cur][0], b2[cur][1]);
        mma_f16(acc[3], wh[cur], b2[cur][2], b2[cur][3]);
        cur = nxt;
    }
}

// ---------------- persistent LSTM kernel ----------------
__global__ void __launch_bounds__(NTHR, 1) lstm_mma()
{
    extern __shared__ __align__(16) uint8_t sm[];
    const int tid  = threadIdx.x;
    const int cta  = blockIdx.x;
    const int lane = tid & 31;
    const int wid  = tid >> 5;
    const int mrow = wid & 1;
    const int wcol = wid >> 1;
    const u32 smA  = smem_u32(sm);

    float* sgate = (float*)(sm + SGATE_B);
    us*    hstg  = (us*)(sm + HSTG_B);          // [128][8] fp16

    const u32 aoffW = (u32)((mrow * 16 + (lane & 15)) * 272 + (lane >> 4) * 16);
    const u32 boffA = (u32)((wcol * 32 + (lane & 7) + ((lane >> 4) & 1) * 8) * 272
                            + ((lane >> 3) & 1) * 16);
    const u32 boffB = boffA + 16 * 272;

    const int j = cta * 8 + wid;
    float bg0[4], bg1[4], bif0[4], bif1[4];
#pragma unroll
    for (int g = 0; g < 4; ++g) {
        bg0[g] = d_bias0[g * Hh + j];
        bg1[g] = d_bias1[g * Hh + j];
    }
#pragma unroll
    for (int p = 0; p < 4; ++p) {
        bif0[p] = d_bi0[(lane + 32 * p) * Hh + j];
        bif1[p] = d_bi1[(lane + 32 * p) * Hh + j];
    }
    float c0[4] = {0.f, 0.f, 0.f, 0.f};
    float c1[4] = {0.f, 0.f, 0.f, 0.f};

#pragma unroll 1
    for (int s = -1; s <= 511 && !g_abort; ++s) {
        const int M = (s < 0) ? 9 : ((s == 511) ? 16 : 25);

        float acc[4][4];
#pragma unroll
        for (int nt = 0; nt < 4; ++nt)
#pragma unroll
            for (int q = 0; q < 4; ++q) acc[nt][q] = 0.f;

        // prologue: pair groups G0=(0,1), G1=(2,3)
        load_m(smA, s, 0, cta, tid);
        load_m(smA, s, 1, cta, tid);
        CP_COMMIT();
        load_m(smA, s, 2, cta, tid);
        load_m(smA, s, 3, cta, tid);
        CP_COMMIT();

#pragma unroll 1
        for (int pm = 0; pm < M; pm += 2) {
            if (pm + 2 < M) CP_WAIT1(); else CP_WAIT0();
            __syncthreads();

            compute_chunk(smA + (u32)(pm & 3) * STG_B, aoffW, boffA, boffB, acc);
            if (pm + 1 < M)
                compute_chunk(smA + (u32)((pm + 1) & 3) * STG_B, aoffW, boffA, boffB, acc);

            // issue next pair (pm+4, pm+5) — unconditional safety post-barrier
            if (pm + 4 < M) {
                load_m(smA, s, pm + 4, cta, tid);
                if (pm + 5 < M) load_m(smA, s, pm + 5, cta, tid);
            }
            CP_COMMIT();

            // ---- L1(s) epilogue after chunk 15 (end of pair 14) ----
            if (s >= 0 && pm == 14) {
                const int t = s, wr = (t & 1) ^ 1;
                {
                    const int row = mrow * 16 + (lane >> 2);
                    const int col = wcol * 32 + (lane & 3) * 2;
#pragma unroll
                    for (int nt = 0; nt < 4; ++nt) {
                        const int cb = col + nt * 8;
                        sgate[row * 132 + cb]           = acc[nt][0];
                        sgate[row * 132 + cb + 1]       = acc[nt][1];
                        sgate[(row + 8) * 132 + cb]     = acc[nt][2];
                        sgate[(row + 8) * 132 + cb + 1] = acc[nt][3];
                    }
                }
                __syncthreads();
#pragma unroll
                for (int p = 0; p < 4; ++p) {
                    const int b = lane + 32 * p;
                    float pi = sgate[(0  + wid) * 132 + b] + bg1[0];
                    float pf = sgate[(8  + wid) * 132 + b] + bg1[1] + bif1[p];
                    float po = sgate[(16 + wid) * 132 + b] + bg1[2];
                    float pg = sgate[(24 + wid) * 132 + b] + bg1[3];
                    float iv = sigf(pi), fv = sigf(pf), ov = sigf(po), gg = tanh_f(pg);
                    float cn = fv * c1[p] + iv * gg;
                    c1[p] = cn;
                    float hv = ov * tanh_f(cn);
                    hstg[b * 8 + wid] = __half_as_ushort(__float2half_rn(hv));
                    if (t == Tt - 1) d_h1f[b * Hh + j] = hv;
                }
                __syncthreads();
                if (tid < 128) {
                    uint4 v = *(const uint4*)(hstg + tid * 8);
                    *(uint4*)(&d_h1[wr][tid][cta * 8]) = v;
                }
#pragma unroll
                for (int nt = 0; nt < 4; ++nt)
#pragma unroll
                    for (int q = 0; q < 4; ++q) acc[nt][q] = 0.f;
            }
        }

        // ---- L0(s+1) epilogue + barrier ----
        if (s < 511) {
            const int t0 = s + 1, wr = (t0 & 1) ^ 1;
            {
                const int row = mrow * 16 + (lane >> 2);
                const int col = wcol * 32 + (lane & 3) * 2;
#pragma unroll
                for (int nt = 0; nt < 4; ++nt) {
                    const int cb = col + nt * 8;
                    sgate[row * 132 + cb]           = acc[nt][0];
                    sgate[row * 132 + cb + 1]       = acc[nt][1];
                    sgate[(row + 8) * 132 + cb]     = acc[nt][2];
                    sgate[(row + 8) * 132 + cb + 1] = acc[nt][3];
                }
            }
            __syncthreads();
#pragma unroll
            for (int p = 0; p < 4; ++p) {
                const int b = lane + 32 * p;
                float pi = sgate[(0  + wid) * 132 + b] + bg0[0];
                float pf = sgate[(8  + wid) * 132 + b] + bg0[1] + bif0[p];
                float po = sgate[(16 + wid) * 132 + b] + bg0[2];
                float pg = sgate[(24 + wid) * 132 + b] + bg0[3];
                float iv = sigf(pi), fv = sigf(pf), ov = sigf(po), gg = tanh_f(pg);
                float cn = fv * c0[p] + iv * gg;
                c0[p] = cn;
                float hv = ov * tanh_f(cn);
                hstg[b * 8 + wid] = __half_as_ushort(__float2half_rn(hv));
            }
            __syncthreads();
            if (tid < 128) {
                uint4 v = *(const uint4*)(hstg + tid * 8);
                *(uint4*)(&d_h0[wr][tid][cta * 8]) = v;
            }
            grid_barrier((u32)(s + 2));
        }
    }
}

// ---------------- fc head ----------------
__global__ void fc_kernel(const float* __restrict__ fcW,
                          const float* __restrict__ fcb,
                          float* __restrict__ out)
{
    __shared__ float red[256];
    int b = blockIdx.x, tid = threadIdx.x;
    float s = 0.f;
    for (int jj = tid; jj < Hh; jj += 256) s += d_h1f[b * Hh + jj] * fcW[jj];
    red[tid] = s;
    __syncthreads();
    for (int o = 128; o > 0; o >>= 1) {
        if (tid < o) red[tid] += red[tid + o];
        __syncthreads();
    }
    if (tid == 0) out[b] = red[0] + fcb[0];
}

// ---------------- launch (5 graph nodes) ----------------
extern "C" void kernel_launch(void* const* d_in, const int* in_sizes, int n_in,
                              void* d_out, int out_size)
{
    const float* x        = (const float*)d_in[0];
    const float* boundary = (const float*)d_in[1];
    const float* Wx0      = (const float*)d_in[2];
    const float* bx0      = (const float*)d_in[3];
    const float* Uh0      = (const float*)d_in[4];
    const float* bh0      = (const float*)d_in[5];
    const float* Wb0      = (const float*)d_in[6];
    const float* bb0      = (const float*)d_in[7];
    const float* Wx1      = (const float*)d_in[8];
    const float* bx1      = (const float*)d_in[9];
    const float* Uh1      = (const float*)d_in[10];
    const float* bh1      = (const float*)d_in[11];
    const float* Wb1      = (const float*)d_in[12];
    const float* bb1      = (const float*)d_in[13];
    const float* fcW      = (const float*)d_in[14];
    const float* fcb      = (const float*)d_in[15];
    float* out            = (float*)d_out;

    cudaFuncSetAttribute(lstm_mma, cudaFuncAttributeMaxDynamicSharedMemorySize, DYN_SMEM);

    setup_misc<<<(Bb * Hh) / 256, 256>>>(boundary, bx0, bh0, bb0, Wb0, bx1, bh1, bb1, Wb1);
    setup_x<<<(Tt * Bb * INP) / 256, 256>>>(x);
    repack_w<<<(128 * 25 * 32 * 128) / 256, 256>>>(Uh0, Wx0, Wx1, Uh1);
    lstm_mma<<<NBLK, NTHR, DYN_SMEM>>>();
    fc_kernel<<<Bb, 256>>>(fcW, fcb, out);
}